// round 3
// baseline (speedup 1.0000x reference)
#include <cuda_runtime.h>
#include <math.h>

#define Bb 2
#define Ss 1024
#define DMm 1024
#define Hh 16
#define Dd 64
#define BH 32
#define Ff 128

typedef unsigned long long u64;

__device__ __forceinline__ u64 dup2(float x) {
    u64 r; asm("mov.b64 %0, {%1, %1};" : "=l"(r) : "f"(x)); return r;
}
__device__ __forceinline__ void fma2(u64 &d, u64 a, u64 b) {
    asm("fma.rn.f32x2 %0, %1, %2, %0;" : "+l"(d) : "l"(a), "l"(b));
}
__device__ __forceinline__ float2 up2(u64 v) {
    float2 f; asm("mov.b64 {%0, %1}, %2;" : "=f"(f.x), "=f"(f.y) : "l"(v)); return f;
}

// ---- scratch ----
__device__ float g_q[BH*Ss*Dd];
__device__ float g_k[BH*Ss*Dd];
__device__ float g_v[BH*Ss*Dd];
__device__ float g_fq[BH*Ss*Ff];
__device__ float g_fk[BH*Ss*Ff];
__device__ float g_ctx[BH*Ss*Dd];
__device__ float g_fks[BH*Ff];
__device__ float g_inv[BH*Ss];

#define OFF_PRED (Bb*Ss*DMm)
#define OFF_TRUE (OFF_PRED + BH*Ss*Ss)

extern __shared__ float dsm[];

// ============================================================
// Kernel 1: QKV projection. BM=128 BN=128 BK=32, 8x8/thread f32x2.
// ============================================================
__global__ __launch_bounds__(256, 2) void qkv_kernel(
    const float* __restrict__ X,
    const float* __restrict__ Wq, const float* __restrict__ bq,
    const float* __restrict__ Wk, const float* __restrict__ bk,
    const float* __restrict__ Wv, const float* __restrict__ bv)
{
    __shared__ __align__(16) float As[32][132];
    __shared__ __align__(16) float Bs[32][132];

    const float* Wm; const float* bias; float* outp;
    if (blockIdx.z == 0)      { Wm = Wq; bias = bq; outp = g_q; }
    else if (blockIdx.z == 1) { Wm = Wk; bias = bk; outp = g_k; }
    else                      { Wm = Wv; bias = bv; outp = g_v; }

    const int m0 = blockIdx.y * 128, n0 = blockIdx.x * 128;
    const int tid = threadIdx.x, tx = tid & 15, ty = tid >> 4;

    u64 acc[4][8];
    #pragma unroll
    for (int p = 0; p < 4; p++)
        #pragma unroll
        for (int j = 0; j < 8; j++) acc[p][j] = 0ull;

    for (int k0 = 0; k0 < 1024; k0 += 32) {
        __syncthreads();
        #pragma unroll
        for (int p = 0; p < 4; p++) {
            int idx = p * 256 + tid;
            int row = idx >> 3, kc = (idx & 7) * 4;
            float4 v = *(const float4*)&X[(size_t)(m0 + row) * 1024 + k0 + kc];
            As[kc][row] = v.x; As[kc+1][row] = v.y; As[kc+2][row] = v.z; As[kc+3][row] = v.w;
        }
        #pragma unroll
        for (int p = 0; p < 4; p++) {
            int idx = p * 256 + tid;
            int row = idx >> 3, kc = (idx & 7) * 4;
            float4 v = *(const float4*)&Wm[(size_t)(n0 + row) * 1024 + k0 + kc];
            Bs[kc][row] = v.x; Bs[kc+1][row] = v.y; Bs[kc+2][row] = v.z; Bs[kc+3][row] = v.w;
        }
        __syncthreads();
        #pragma unroll 8
        for (int k = 0; k < 32; k++) {
            ulonglong2 a0 = *(const ulonglong2*)&As[k][ty * 8];
            ulonglong2 a1 = *(const ulonglong2*)&As[k][ty * 8 + 4];
            u64 ap[4] = {a0.x, a0.y, a1.x, a1.y};
            float4 b0 = *(const float4*)&Bs[k][tx * 4];
            float4 b1 = *(const float4*)&Bs[k][tx * 4 + 64];
            u64 bd[8] = {dup2(b0.x), dup2(b0.y), dup2(b0.z), dup2(b0.w),
                         dup2(b1.x), dup2(b1.y), dup2(b1.z), dup2(b1.w)};
            #pragma unroll
            for (int p = 0; p < 4; p++)
                #pragma unroll
                for (int j = 0; j < 8; j++) fma2(acc[p][j], ap[p], bd[j]);
        }
    }

    float4 bv0 = *(const float4*)&bias[n0 + tx * 4];
    float4 bv1 = *(const float4*)&bias[n0 + 64 + tx * 4];
    const int na = n0 + tx * 4, nb = n0 + 64 + tx * 4;
    const int ha = na >> 6, hb = nb >> 6;
    #pragma unroll
    for (int p = 0; p < 4; p++) {
        float2 c[8];
        #pragma unroll
        for (int j = 0; j < 8; j++) c[j] = up2(acc[p][j]);
        int m = m0 + ty * 8 + 2 * p;
        int b_ = m >> 10, s = m & 1023;
        float4 r;
        r.x = c[0].x + bv0.x; r.y = c[1].x + bv0.y; r.z = c[2].x + bv0.z; r.w = c[3].x + bv0.w;
        *(float4*)&outp[(((size_t)(b_ * Hh + ha)) * Ss + s) * Dd + (na & 63)] = r;
        r.x = c[4].x + bv1.x; r.y = c[5].x + bv1.y; r.z = c[6].x + bv1.z; r.w = c[7].x + bv1.w;
        *(float4*)&outp[(((size_t)(b_ * Hh + hb)) * Ss + s) * Dd + (nb & 63)] = r;
        r.x = c[0].y + bv0.x; r.y = c[1].y + bv0.y; r.z = c[2].y + bv0.z; r.w = c[3].y + bv0.w;
        *(float4*)&outp[(((size_t)(b_ * Hh + ha)) * Ss + s + 1) * Dd + (na & 63)] = r;
        r.x = c[4].y + bv1.x; r.y = c[5].y + bv1.y; r.z = c[6].y + bv1.z; r.w = c[7].y + bv1.w;
        *(float4*)&outp[(((size_t)(b_ * Hh + hb)) * Ss + s + 1) * Dd + (nb & 63)] = r;
    }
}

// ============================================================
// Kernel 2: hedgehog feature map (unchanged structure).
// ============================================================
__global__ __launch_bounds__(256) void feat_kernel(
    const float* __restrict__ Wfq, const float* __restrict__ bfq,
    const float* __restrict__ Wfk, const float* __restrict__ bfk)
{
    const float* Wf; const float* bf; const float* src; float* dst;
    if (blockIdx.y == 0) { Wf = Wfq; bf = bfq; src = g_q; dst = g_fq; }
    else                 { Wf = Wfk; bf = bfk; src = g_k; dst = g_fk; }

    __shared__ float Wt[64][65];
    __shared__ float bsm[64];
    __shared__ float qs[4][64];

    const int tid = threadIdx.x;
    #pragma unroll
    for (int p = 0; p < 16; p++) {
        int idx = p * 256 + tid;
        Wt[idx & 63][idx >> 6] = Wf[idx];
    }
    if (tid < 64) bsm[tid] = bf[tid];

    const int rowbase = blockIdx.x * 128;
    const int e = tid & 63, rr = tid >> 6;

    for (int r0 = 0; r0 < 128; r0 += 4) {
        __syncthreads();
        int row = rowbase + r0 + rr;
        qs[rr][e] = src[(size_t)row * 64 + e];
        __syncthreads();
        float y = bsm[e];
        #pragma unroll
        for (int d = 0; d < 64; d++) y += Wt[d][e] * qs[rr][d];
        dst[(size_t)row * 128 + e]      = expf(y);
        dst[(size_t)row * 128 + 64 + e] = expf(-y);
    }
}

// ============================================================
// Kernel 3: fk column sums per head:  fksum[bh][e] = sum_s fk[bh][s][e]
// ============================================================
__global__ __launch_bounds__(256) void fksum_kernel()
{
    const int bh = blockIdx.x, tid = threadIdx.x;
    const int e = tid & 127, part = tid >> 7;
    const float* fkp = g_fk + (size_t)bh * Ss * Ff;
    float s = 0.f;
    for (int r = part; r < 1024; r += 2) s += fkp[(size_t)r * 128 + e];
    __shared__ float sm[256];
    sm[tid] = s;
    __syncthreads();
    if (tid < 128) g_fks[bh * 128 + tid] = sm[tid] + sm[tid + 128];
}

// ============================================================
// Kernel 4: true attention pass 1: P = exp(QK^T/8) -> out, rowsum -> g_inv.
// BM=128 BN=128 K=64. dyn smem: Qs[64][132] + Ks[64][132].
// ============================================================
__global__ __launch_bounds__(256, 2) void true_exp_kernel(float* __restrict__ outT)
{
    float* Qs = dsm;            // [64][132] (Q^T, prescaled by 1/8)
    float* Ks = dsm + 64 * 132; // [64][132]

    const int bh = blockIdx.y, m0 = blockIdx.x * 128;
    const int tid = threadIdx.x, tx = tid & 15, ty = tid >> 4;

    const float* qp = g_q + (size_t)bh * Ss * Dd;
    const float* kp = g_k + (size_t)bh * Ss * Dd;
    float* trow = outT + (size_t)bh * Ss * Ss;

    #pragma unroll
    for (int p = 0; p < 8; p++) {
        int idx = p * 256 + tid;
        int row = idx >> 4, c = (idx & 15) * 4;
        float4 v = *(const float4*)&qp[(size_t)(m0 + row) * 64 + c];
        Qs[(c+0)*132 + row] = v.x * 0.125f; Qs[(c+1)*132 + row] = v.y * 0.125f;
        Qs[(c+2)*132 + row] = v.z * 0.125f; Qs[(c+3)*132 + row] = v.w * 0.125f;
    }

    float rsum[8];
    #pragma unroll
    for (int i = 0; i < 8; i++) rsum[i] = 0.f;

    for (int nt = 0; nt < 8; nt++) {
        const int n0 = nt * 128;
        __syncthreads();
        #pragma unroll
        for (int p = 0; p < 8; p++) {
            int idx = p * 256 + tid;
            int row = idx >> 4, c = (idx & 15) * 4;
            float4 v = *(const float4*)&kp[(size_t)(n0 + row) * 64 + c];
            Ks[(c+0)*132 + row] = v.x; Ks[(c+1)*132 + row] = v.y;
            Ks[(c+2)*132 + row] = v.z; Ks[(c+3)*132 + row] = v.w;
        }
        __syncthreads();

        u64 acc[4][8];
        #pragma unroll
        for (int p = 0; p < 4; p++)
            #pragma unroll
            for (int j = 0; j < 8; j++) acc[p][j] = 0ull;

        #pragma unroll 8
        for (int k = 0; k < 64; k++) {
            ulonglong2 a0 = *(const ulonglong2*)&Qs[k * 132 + ty * 8];
            ulonglong2 a1 = *(const ulonglong2*)&Qs[k * 132 + ty * 8 + 4];
            u64 ap[4] = {a0.x, a0.y, a1.x, a1.y};
            float4 b0 = *(const float4*)&Ks[k * 132 + tx * 4];
            float4 b1 = *(const float4*)&Ks[k * 132 + tx * 4 + 64];
            u64 bd[8] = {dup2(b0.x), dup2(b0.y), dup2(b0.z), dup2(b0.w),
                         dup2(b1.x), dup2(b1.y), dup2(b1.z), dup2(b1.w)};
            #pragma unroll
            for (int p = 0; p < 4; p++)
                #pragma unroll
                for (int j = 0; j < 8; j++) fma2(acc[p][j], ap[p], bd[j]);
        }

        #pragma unroll
        for (int p = 0; p < 4; p++) {
            float2 c[8];
            #pragma unroll
            for (int j = 0; j < 8; j++) c[j] = up2(acc[p][j]);
            float e0[8], e1[8];
            #pragma unroll
            for (int j = 0; j < 8; j++) { e0[j] = __expf(c[j].x); e1[j] = __expf(c[j].y); }
            rsum[2*p]   += e0[0]+e0[1]+e0[2]+e0[3]+e0[4]+e0[5]+e0[6]+e0[7];
            rsum[2*p+1] += e1[0]+e1[1]+e1[2]+e1[3]+e1[4]+e1[5]+e1[6]+e1[7];
            size_t r0 = (size_t)(m0 + ty * 8 + 2 * p) * 1024 + n0;
            *(float4*)&trow[r0 + tx * 4]        = make_float4(e0[0], e0[1], e0[2], e0[3]);
            *(float4*)&trow[r0 + 64 + tx * 4]   = make_float4(e0[4], e0[5], e0[6], e0[7]);
            *(float4*)&trow[r0 + 1024 + tx * 4]      = make_float4(e1[0], e1[1], e1[2], e1[3]);
            *(float4*)&trow[r0 + 1024 + 64 + tx * 4] = make_float4(e1[4], e1[5], e1[6], e1[7]);
        }
    }

    #pragma unroll
    for (int i = 0; i < 8; i++) {
        float v = rsum[i];
        #pragma unroll
        for (int off = 1; off < 16; off <<= 1)
            v += __shfl_xor_sync(0xffffffffu, v, off);
        if (tx == 0) g_inv[bh * 1024 + m0 + ty * 8 + i] = 1.f / v;
    }
}

// ============================================================
// Kernel 5: hedgehog pred, one pass. denom via fq . fksum.
// BM=128 BN=128 K=128 (Fk staged in two 64-k chunks -> 2 blocks/SM).
// dyn smem: FqT[128][132] + FkT[64][132]
// ============================================================
__global__ __launch_bounds__(256, 2) void pred_kernel(float* __restrict__ outP)
{
    float* FqT = dsm;             // [128 k][132]
    float* FkT = dsm + 128 * 132; // [64 k][132]
    __shared__ float fks[128];
    __shared__ float invsm[128];

    const int bh = blockIdx.y, m0 = blockIdx.x * 128;
    const int tid = threadIdx.x, tx = tid & 15, ty = tid >> 4;

    const float* fqp = g_fq + (size_t)bh * Ss * Ff;
    const float* fkp = g_fk + (size_t)bh * Ss * Ff;
    float* prow = outP + (size_t)bh * Ss * Ss;

    if (tid < 128) fks[tid] = g_fks[bh * 128 + tid];

    #pragma unroll
    for (int p = 0; p < 16; p++) {
        int idx = p * 256 + tid;
        int row = idx >> 5, c = (idx & 31) * 4;
        float4 v = *(const float4*)&fqp[(size_t)(m0 + row) * 128 + c];
        FqT[(c+0)*132 + row] = v.x; FqT[(c+1)*132 + row] = v.y;
        FqT[(c+2)*132 + row] = v.z; FqT[(c+3)*132 + row] = v.w;
    }
    __syncthreads();

    if (tid < 128) {
        float s = 0.f;
        #pragma unroll 8
        for (int k = 0; k < 128; k++) s += FqT[k * 132 + tid] * fks[k];
        invsm[tid] = 1.f / s;
    }
    __syncthreads();

    float invr[8];
    #pragma unroll
    for (int i = 0; i < 8; i++) invr[i] = invsm[ty * 8 + i];

    for (int nt = 0; nt < 8; nt++) {
        const int n0 = nt * 128;
        u64 acc[4][8];
        #pragma unroll
        for (int p = 0; p < 4; p++)
            #pragma unroll
            for (int j = 0; j < 8; j++) acc[p][j] = 0ull;

        #pragma unroll
        for (int half = 0; half < 2; half++) {
            __syncthreads();
            #pragma unroll
            for (int p = 0; p < 8; p++) {
                int idx = p * 256 + tid;
                int row = idx >> 4, c = (idx & 15) * 4;   // row: n (0..127), c: k (0..60)
                float4 v = *(const float4*)&fkp[(size_t)(n0 + row) * 128 + half * 64 + c];
                FkT[(c+0)*132 + row] = v.x; FkT[(c+1)*132 + row] = v.y;
                FkT[(c+2)*132 + row] = v.z; FkT[(c+3)*132 + row] = v.w;
            }
            __syncthreads();
            #pragma unroll 8
            for (int kk = 0; kk < 64; kk++) {
                int kg = half * 64 + kk;
                ulonglong2 a0 = *(const ulonglong2*)&FqT[kg * 132 + ty * 8];
                ulonglong2 a1 = *(const ulonglong2*)&FqT[kg * 132 + ty * 8 + 4];
                u64 ap[4] = {a0.x, a0.y, a1.x, a1.y};
                float4 b0 = *(const float4*)&FkT[kk * 132 + tx * 4];
                float4 b1 = *(const float4*)&FkT[kk * 132 + tx * 4 + 64];
                u64 bd[8] = {dup2(b0.x), dup2(b0.y), dup2(b0.z), dup2(b0.w),
                             dup2(b1.x), dup2(b1.y), dup2(b1.z), dup2(b1.w)};
                #pragma unroll
                for (int p = 0; p < 4; p++)
                    #pragma unroll
                    for (int j = 0; j < 8; j++) fma2(acc[p][j], ap[p], bd[j]);
            }
        }

        #pragma unroll
        for (int p = 0; p < 4; p++) {
            float2 c[8];
            #pragma unroll
            for (int j = 0; j < 8; j++) c[j] = up2(acc[p][j]);
            float i0 = invr[2*p], i1 = invr[2*p+1];
            size_t r0 = (size_t)(m0 + ty * 8 + 2 * p) * 1024 + n0;
            *(float4*)&prow[r0 + tx * 4]      = make_float4(c[0].x*i0, c[1].x*i0, c[2].x*i0, c[3].x*i0);
            *(float4*)&prow[r0 + 64 + tx * 4] = make_float4(c[4].x*i0, c[5].x*i0, c[6].x*i0, c[7].x*i0);
            *(float4*)&prow[r0 + 1024 + tx * 4]      = make_float4(c[0].y*i1, c[1].y*i1, c[2].y*i1, c[3].y*i1);
            *(float4*)&prow[r0 + 1024 + 64 + tx * 4] = make_float4(c[4].y*i1, c[5].y*i1, c[6].y*i1, c[7].y*i1);
        }
    }
}

// ============================================================
// Kernel 6: ctx = Pnorm @ V, normalizing trow in place while loading.
// BM=128 BN=64(=Dd) BK=32, 8x4/thread f32x2.
// ============================================================
__global__ __launch_bounds__(256, 2) void ctx_kernel(float* __restrict__ outT)
{
    __shared__ __align__(16) float As[32][132];
    __shared__ __align__(16) float Bs[32][68];
    __shared__ float invsm[128];

    const int bh = blockIdx.y, m0 = blockIdx.x * 128;
    const int tid = threadIdx.x, tx = tid & 15, ty = tid >> 4;

    float* trow = outT + (size_t)bh * Ss * Ss;
    const float* vp = g_v + (size_t)bh * Ss * Dd;

    if (tid < 128) invsm[tid] = g_inv[bh * 1024 + m0 + tid];
    __syncthreads();

    u64 acc[4][4];
    #pragma unroll
    for (int p = 0; p < 4; p++)
        #pragma unroll
        for (int j = 0; j < 4; j++) acc[p][j] = 0ull;

    for (int k0 = 0; k0 < 1024; k0 += 32) {
        __syncthreads();
        #pragma unroll
        for (int p = 0; p < 4; p++) {
            int idx = p * 256 + tid;
            int row = idx >> 3, kc = (idx & 7) * 4;
            size_t ga = (size_t)(m0 + row) * 1024 + k0 + kc;
            float4 v = *(const float4*)&trow[ga];
            float iv = invsm[row];
            v.x *= iv; v.y *= iv; v.z *= iv; v.w *= iv;
            *(float4*)&trow[ga] = v;                 // normalized write-back
            As[kc][row] = v.x; As[kc+1][row] = v.y; As[kc+2][row] = v.z; As[kc+3][row] = v.w;
        }
        #pragma unroll
        for (int p = 0; p < 2; p++) {
            int idx = p * 256 + tid;
            int row = idx >> 4, c = (idx & 15) * 4;
            *(float4*)&Bs[row][c] = *(const float4*)&vp[(size_t)(k0 + row) * 64 + c];
        }
        __syncthreads();
        #pragma unroll 8
        for (int k = 0; k < 32; k++) {
            ulonglong2 a0 = *(const ulonglong2*)&As[k][ty * 8];
            ulonglong2 a1 = *(const ulonglong2*)&As[k][ty * 8 + 4];
            u64 ap[4] = {a0.x, a0.y, a1.x, a1.y};
            float4 b = *(const float4*)&Bs[k][tx * 4];
            u64 bd[4] = {dup2(b.x), dup2(b.y), dup2(b.z), dup2(b.w)};
            #pragma unroll
            for (int p = 0; p < 4; p++)
                #pragma unroll
                for (int j = 0; j < 4; j++) fma2(acc[p][j], ap[p], bd[j]);
        }
    }

    float* cp = g_ctx + (size_t)bh * Ss * Dd;
    #pragma unroll
    for (int p = 0; p < 4; p++) {
        float2 c0 = up2(acc[p][0]), c1 = up2(acc[p][1]), c2 = up2(acc[p][2]), c3 = up2(acc[p][3]);
        int m = m0 + ty * 8 + 2 * p;
        *(float4*)&cp[(size_t)m * 64 + tx * 4]       = make_float4(c0.x, c1.x, c2.x, c3.x);
        *(float4*)&cp[(size_t)(m + 1) * 64 + tx * 4] = make_float4(c0.y, c1.y, c2.y, c3.y);
    }
}

// ============================================================
// Kernel 7: output projection. Same shape as qkv, A from g_ctx head layout.
// ============================================================
__global__ __launch_bounds__(256, 2) void outproj_kernel(
    const float* __restrict__ Wo, const float* __restrict__ bo,
    float* __restrict__ out)
{
    __shared__ __align__(16) float As[32][132];
    __shared__ __align__(16) float Bs[32][132];

    const int m0 = blockIdx.y * 128, n0 = blockIdx.x * 128;
    const int tid = threadIdx.x, tx = tid & 15, ty = tid >> 4;

    u64 acc[4][8];
    #pragma unroll
    for (int p = 0; p < 4; p++)
        #pragma unroll
        for (int j = 0; j < 8; j++) acc[p][j] = 0ull;

    for (int k0 = 0; k0 < 1024; k0 += 32) {
        const int h = k0 >> 6, dbase = k0 & 63;
        __syncthreads();
        #pragma unroll
        for (int p = 0; p < 4; p++) {
            int idx = p * 256 + tid;
            int row = idx >> 3, kc = (idx & 7) * 4;
            int m = m0 + row;
            int b_ = m >> 10, s = m & 1023;
            float4 v = *(const float4*)&g_ctx[(((size_t)(b_ * Hh + h)) * Ss + s) * 64 + dbase + kc];
            As[kc][row] = v.x; As[kc+1][row] = v.y; As[kc+2][row] = v.z; As[kc+3][row] = v.w;
        }
        #pragma unroll
        for (int p = 0; p < 4; p++) {
            int idx = p * 256 + tid;
            int row = idx >> 3, kc = (idx & 7) * 4;
            float4 v = *(const float4*)&Wo[(size_t)(n0 + row) * 1024 + k0 + kc];
            Bs[kc][row] = v.x; Bs[kc+1][row] = v.y; Bs[kc+2][row] = v.z; Bs[kc+3][row] = v.w;
        }
        __syncthreads();
        #pragma unroll 8
        for (int k = 0; k < 32; k++) {
            ulonglong2 a0 = *(const ulonglong2*)&As[k][ty * 8];
            ulonglong2 a1 = *(const ulonglong2*)&As[k][ty * 8 + 4];
            u64 ap[4] = {a0.x, a0.y, a1.x, a1.y};
            float4 b0 = *(const float4*)&Bs[k][tx * 4];
            float4 b1 = *(const float4*)&Bs[k][tx * 4 + 64];
            u64 bd[8] = {dup2(b0.x), dup2(b0.y), dup2(b0.z), dup2(b0.w),
                         dup2(b1.x), dup2(b1.y), dup2(b1.z), dup2(b1.w)};
            #pragma unroll
            for (int p = 0; p < 4; p++)
                #pragma unroll
                for (int j = 0; j < 8; j++) fma2(acc[p][j], ap[p], bd[j]);
        }
    }

    float4 bv0 = *(const float4*)&bo[n0 + tx * 4];
    float4 bv1 = *(const float4*)&bo[n0 + 64 + tx * 4];
    #pragma unroll
    for (int p = 0; p < 4; p++) {
        float2 c[8];
        #pragma unroll
        for (int j = 0; j < 8; j++) c[j] = up2(acc[p][j]);
        size_t m = (size_t)(m0 + ty * 8 + 2 * p);
        *(float4*)&out[m * 1024 + n0 + tx * 4] =
            make_float4(c[0].x + bv0.x, c[1].x + bv0.y, c[2].x + bv0.z, c[3].x + bv0.w);
        *(float4*)&out[m * 1024 + n0 + 64 + tx * 4] =
            make_float4(c[4].x + bv1.x, c[5].x + bv1.y, c[6].x + bv1.z, c[7].x + bv1.w);
        *(float4*)&out[(m + 1) * 1024 + n0 + tx * 4] =
            make_float4(c[0].y + bv0.x, c[1].y + bv0.y, c[2].y + bv0.z, c[3].y + bv0.w);
        *(float4*)&out[(m + 1) * 1024 + n0 + 64 + tx * 4] =
            make_float4(c[4].y + bv1.x, c[5].y + bv1.y, c[6].y + bv1.z, c[7].y + bv1.w);
    }
}

// ============================================================
extern "C" void kernel_launch(void* const* d_in, const int* in_sizes, int n_in,
                              void* d_out, int out_size)
{
    const float* hs  = (const float*)d_in[0];
    const float* Wq  = (const float*)d_in[1];
    const float* bq  = (const float*)d_in[2];
    const float* Wk  = (const float*)d_in[3];
    const float* bk  = (const float*)d_in[4];
    const float* Wv  = (const float*)d_in[5];
    const float* bv  = (const float*)d_in[6];
    const float* Wo  = (const float*)d_in[7];
    const float* bo  = (const float*)d_in[8];
    const float* Wfq = (const float*)d_in[9];
    const float* bfq = (const float*)d_in[10];
    const float* Wfk = (const float*)d_in[11];
    const float* bfk = (const float*)d_in[12];
    float* out = (float*)d_out;

    const int smem_true = 2 * 64 * 132 * (int)sizeof(float);        // 67584
    const int smem_pred = (128 + 64) * 132 * (int)sizeof(float);    // 101376
    cudaFuncSetAttribute(true_exp_kernel, cudaFuncAttributeMaxDynamicSharedMemorySize, smem_true);
    cudaFuncSetAttribute(pred_kernel,     cudaFuncAttributeMaxDynamicSharedMemorySize, smem_pred);

    qkv_kernel<<<dim3(8, 16, 3), 256>>>(hs, Wq, bq, Wk, bk, Wv, bv);
    feat_kernel<<<dim3(256, 2), 256>>>(Wfq, bfq, Wfk, bfk);
    fksum_kernel<<<32, 256>>>();
    true_exp_kernel<<<dim3(8, 32), 256, smem_true>>>(out + OFF_TRUE);
    pred_kernel<<<dim3(8, 32), 256, smem_pred>>>(out + OFF_PRED);
    ctx_kernel<<<dim3(8, 32), 256>>>(out + OFF_TRUE);
    outproj_kernel<<<dim3(8, 16), 256>>>(Wo, bo, out);
}

// round 5
// speedup vs baseline: 1.0303x; 1.0303x over previous
#include <cuda_runtime.h>
#include <cuda_bf16.h>
#include <math.h>
#include <stdint.h>

#define Ss 1024
#define Hh 16
#define BH 32
#define LD 40   // bf16 elems per smem row (16B-odd stride: conflict-free ldmatrix)
typedef __nv_bfloat16 bf;
typedef unsigned int u32;

#define OFF_PRED (2048*1024)
#define OFF_TRUE (OFF_PRED + 32*1024*1024)

// ---------------- scratch ----------------
__device__ float g_q[BH*Ss*64], g_k[BH*Ss*64], g_v[BH*Ss*64];
__device__ bf g_qhi[BH*Ss*64], g_qlo[BH*Ss*64];     // prescaled by 1/8
__device__ bf g_khi[BH*Ss*64], g_klo[BH*Ss*64];
__device__ bf g_vthi[BH*64*Ss], g_vtlo[BH*64*Ss];   // [bh][d][s]
__device__ bf g_Xhi[2048*1024], g_Xlo[2048*1024];
__device__ bf g_Whi[4][1024*1024], g_Wlo[4][1024*1024];
__device__ bf g_fqhi[BH*Ss*128], g_fqlo[BH*Ss*128];
__device__ bf g_fkhi[BH*Ss*128], g_fklo[BH*Ss*128];
__device__ bf g_chi[BH*Ss*64], g_clo[BH*Ss*64];
__device__ float g_fks[BH*128], g_inv[BH*Ss], g_pinv[BH*Ss];

// ---------------- helpers ----------------
__device__ __forceinline__ u32 s2u(const void* p) {
    u32 r; asm("{ .reg .u64 t; cvta.to.shared.u64 t, %1; cvt.u32.u64 %0, t; }" : "=r"(r) : "l"(p)); return r;
}
__device__ __forceinline__ void ldsm4(u32 a, u32& r0, u32& r1, u32& r2, u32& r3) {
    asm volatile("ldmatrix.sync.aligned.m8n8.x4.shared.b16 {%0,%1,%2,%3}, [%4];"
        : "=r"(r0), "=r"(r1), "=r"(r2), "=r"(r3) : "r"(a));
}
__device__ __forceinline__ void mmabf(float* d, const u32* a, const u32* b) {
    asm volatile("mma.sync.aligned.m16n8k16.row.col.f32.bf16.bf16.f32 "
        "{%0,%1,%2,%3}, {%4,%5,%6,%7}, {%8,%9}, {%0,%1,%2,%3};"
        : "+f"(d[0]), "+f"(d[1]), "+f"(d[2]), "+f"(d[3])
        : "r"(a[0]), "r"(a[1]), "r"(a[2]), "r"(a[3]), "r"(b[0]), "r"(b[1]));
}
__device__ __forceinline__ void split2(float x, float y, u32& hi, u32& lo) {
    bf hx = __float2bfloat16(x), hy = __float2bfloat16(y);
    bf lx = __float2bfloat16(x - __bfloat162float(hx));
    bf ly = __float2bfloat16(y - __bfloat162float(hy));
    hi = (u32)__bfloat16_as_ushort(hx) | ((u32)__bfloat16_as_ushort(hy) << 16);
    lo = (u32)__bfloat16_as_ushort(lx) | ((u32)__bfloat16_as_ushort(ly) << 16);
}

// gmem (K-major, row stride ldg elems) -> smem [rows][LD], 32-k chunk
__device__ __forceinline__ void ldtile32(const bf* __restrict__ g, int ldg, bf* s, int rows) {
    for (int i = threadIdx.x; i < rows * 4; i += 256) {
        int r = i >> 2, c = (i & 3) << 3;
        *(uint4*)&s[r * LD + c] = *(const uint4*)&g[(size_t)r * ldg + c];
    }
}

// warp computes 32(m) x NF*8(n) over a 32-k chunk with hi/lo 3-product emulation
template<int NF>
__device__ __forceinline__ void mma_chunk(
    float (&acc)[2][NF][4],
    const bf* Ah, const bf* Al, const bf* Bh, const bf* Bl,
    int wm, int wn, int lane)
{
    const u32 ahb = s2u(Ah) + (u32)(wm * 32 * LD * 2);
    const u32 alb = s2u(Al) + (u32)(wm * 32 * LD * 2);
    const u32 bhb = s2u(Bh) + (u32)(wn * NF * 8 * LD * 2);
    const u32 blb = s2u(Bl) + (u32)(wn * NF * 8 * LD * 2);
    const u32 aoff = (u32)(((lane & 15) * LD + ((lane >> 4) << 3)) * 2);
    const u32 boff = (u32)((((lane & 7) + ((lane >> 4) << 3)) * LD + (((lane >> 3) & 1) << 3)) * 2);
    #pragma unroll
    for (int kk = 0; kk < 32; kk += 16) {
        u32 ah[2][4], al[2][4], bhf[NF][2], blf[NF][2];
        #pragma unroll
        for (int i = 0; i < 2; i++) {
            ldsm4(ahb + aoff + kk * 2 + i * 16 * LD * 2, ah[i][0], ah[i][1], ah[i][2], ah[i][3]);
            ldsm4(alb + aoff + kk * 2 + i * 16 * LD * 2, al[i][0], al[i][1], al[i][2], al[i][3]);
        }
        #pragma unroll
        for (int j = 0; j < NF; j += 2) {
            ldsm4(bhb + boff + kk * 2 + j * 8 * LD * 2, bhf[j][0], bhf[j][1], bhf[j+1][0], bhf[j+1][1]);
            ldsm4(blb + boff + kk * 2 + j * 8 * LD * 2, blf[j][0], blf[j][1], blf[j+1][0], blf[j+1][1]);
        }
        #pragma unroll
        for (int i = 0; i < 2; i++)
            #pragma unroll
            for (int j = 0; j < NF; j++) {
                mmabf(acc[i][j], ah[i], bhf[j]);
                mmabf(acc[i][j], ah[i], blf[j]);
                mmabf(acc[i][j], al[i], bhf[j]);
            }
    }
}

// ============================================================
__global__ __launch_bounds__(256) void ksplit(const float* __restrict__ src,
                                              bf* __restrict__ hi, bf* __restrict__ lo, int n4)
{
    int i = blockIdx.x * 256 + threadIdx.x;
    if (i < n4) {
        float4 v = ((const float4*)src)[i];
        u32 h0, l0, h1, l1;
        split2(v.x, v.y, h0, l0);
        split2(v.z, v.w, h1, l1);
        ((uint2*)hi)[i] = make_uint2(h0, h1);
        ((uint2*)lo)[i] = make_uint2(l0, l1);
    }
}

// ============================================================
// QKV: C = X @ W^T + b. grid(8n,16m,3z).
// ============================================================
__global__ __launch_bounds__(256) void qkv_mma(
    const float* __restrict__ bq, const float* __restrict__ bk, const float* __restrict__ bv)
{
    __shared__ bf Ah[128*LD], Al[128*LD], Bh2[128*LD], Bl2[128*LD];
    const int tid = threadIdx.x, lane = tid & 31, wid = tid >> 5;
    const int wm = wid & 3, wn = wid >> 2;
    const int g = lane >> 2, ti = lane & 3;
    const int z = blockIdx.z, m0 = blockIdx.y * 128, n0 = blockIdx.x * 128;
    const bf* Whi = g_Whi[z]; const bf* Wlo = g_Wlo[z];
    const float* bias = z == 0 ? bq : (z == 1 ? bk : bv);

    float acc[2][8][4];
    #pragma unroll
    for (int i = 0; i < 2; i++)
        #pragma unroll
        for (int j = 0; j < 8; j++)
            #pragma unroll
            for (int r = 0; r < 4; r++) acc[i][j][r] = 0.f;

    for (int k0 = 0; k0 < 1024; k0 += 32) {
        ldtile32(g_Xhi + (size_t)m0 * 1024 + k0, 1024, Ah, 128);
        ldtile32(g_Xlo + (size_t)m0 * 1024 + k0, 1024, Al, 128);
        ldtile32(Whi + (size_t)n0 * 1024 + k0, 1024, Bh2, 128);
        ldtile32(Wlo + (size_t)n0 * 1024 + k0, 1024, Bl2, 128);
        __syncthreads();
        mma_chunk<8>(acc, Ah, Al, Bh2, Bl2, wm, wn, lane);
        __syncthreads();
    }

    #pragma unroll
    for (int i = 0; i < 2; i++)
        #pragma unroll
        for (int j = 0; j < 8; j++) {
            const int col = n0 + wn * 64 + j * 8 + ti * 2;
            const int h = col >> 6, d = col & 63;
            const float b0v = bias[col], b1v = bias[col + 1];
            #pragma unroll
            for (int hr = 0; hr < 2; hr++) {
                const int row = m0 + wm * 32 + i * 16 + g + hr * 8;
                const int b_ = row >> 10, s = row & 1023;
                const size_t ob = ((size_t)(b_ * Hh + h) * Ss + s) * 64 + d;
                const float v0 = acc[i][j][hr * 2] + b0v, v1 = acc[i][j][hr * 2 + 1] + b1v;
                u32 h2, l2;
                if (z == 0) {
                    *(float2*)&g_q[ob] = make_float2(v0, v1);
                    split2(v0 * 0.125f, v1 * 0.125f, h2, l2);
                    *(u32*)&g_qhi[ob] = h2; *(u32*)&g_qlo[ob] = l2;
                } else if (z == 1) {
                    *(float2*)&g_k[ob] = make_float2(v0, v1);
                    split2(v0, v1, h2, l2);
                    *(u32*)&g_khi[ob] = h2; *(u32*)&g_klo[ob] = l2;
                } else {
                    *(float2*)&g_v[ob] = make_float2(v0, v1);
                }
            }
        }
}

// ============================================================
// feature map -> split bf16
// ============================================================
__global__ __launch_bounds__(256) void feat_kernel(
    const float* __restrict__ Wfq, const float* __restrict__ bfq,
    const float* __restrict__ Wfk, const float* __restrict__ bfk)
{
    const float* Wf; const float* bfp; const float* src; bf *dh, *dl;
    if (blockIdx.y == 0) { Wf = Wfq; bfp = bfq; src = g_q; dh = g_fqhi; dl = g_fqlo; }
    else                 { Wf = Wfk; bfp = bfk; src = g_k; dh = g_fkhi; dl = g_fklo; }

    __shared__ float Wt[64][65];
    __shared__ float bsm[64];
    __shared__ float qs[4][64];

    const int tid = threadIdx.x;
    #pragma unroll
    for (int p = 0; p < 16; p++) {
        int idx = p * 256 + tid;
        Wt[idx & 63][idx >> 6] = Wf[idx];
    }
    if (tid < 64) bsm[tid] = bfp[tid];

    const int rowbase = blockIdx.x * 128;
    const int e = tid & 63, rr = tid >> 6;

    for (int r0 = 0; r0 < 128; r0 += 4) {
        __syncthreads();
        int row = rowbase + r0 + rr;
        qs[rr][e] = src[(size_t)row * 64 + e];
        __syncthreads();
        float y = bsm[e];
        #pragma unroll
        for (int d = 0; d < 64; d++) y += Wt[d][e] * qs[rr][d];
        float e0 = expf(y), e1 = expf(-y);
        bf h0 = __float2bfloat16(e0), h1 = __float2bfloat16(e1);
        size_t o = (size_t)row * 128 + e;
        dh[o] = h0;      dl[o] = __float2bfloat16(e0 - __bfloat162float(h0));
        dh[o + 64] = h1; dl[o + 64] = __float2bfloat16(e1 - __bfloat162float(h1));
    }
}

// ============================================================
// V transpose + split: g_v [bh][s][64] -> vt [bh][64][s] hi/lo
// ============================================================
__global__ __launch_bounds__(256) void vtrans()
{
    __shared__ float t[128][65];
    const int bh = blockIdx.x, s0 = blockIdx.y * 128, tid = threadIdx.x;
    for (int i = tid; i < 2048; i += 256) {
        int r = i >> 4, c = (i & 15) * 4;
        float4 v = *(const float4*)&g_v[((size_t)bh * Ss + s0 + r) * 64 + c];
        t[r][c] = v.x; t[r][c+1] = v.y; t[r][c+2] = v.z; t[r][c+3] = v.w;
    }
    __syncthreads();
    for (int i = tid; i < 1024; i += 256) {
        int d = i >> 4, sb = (i & 15) * 8;
        __align__(16) unsigned short hh[8], ll[8];
        #pragma unroll
        for (int j = 0; j < 8; j++) {
            float x = t[sb + j][d];
            bf h = __float2bfloat16(x);
            hh[j] = __bfloat16_as_ushort(h);
            ll[j] = __bfloat16_as_ushort(__float2bfloat16(x - __bfloat162float(h)));
        }
        size_t ob = ((size_t)bh * 64 + d) * Ss + s0 + sb;
        *(uint4*)&g_vthi[ob] = *(uint4*)hh;
        *(uint4*)&g_vtlo[ob] = *(uint4*)ll;
    }
}

// ============================================================
__global__ __launch_bounds__(256) void fksum_kernel()
{
    const int bh = blockIdx.x, tid = threadIdx.x;
    const int e = tid & 127, part = tid >> 7;
    const bf* fh = g_fkhi + (size_t)bh * Ss * 128;
    const bf* fl = g_fklo + (size_t)bh * Ss * 128;
    float s = 0.f;
    for (int r = part; r < 1024; r += 2) {
        size_t o = (size_t)r * 128 + e;
        s += __bfloat162float(fh[o]) + __bfloat162float(fl[o]);
    }
    __shared__ float sm[256];
    sm[tid] = s;
    __syncthreads();
    if (tid < 128) g_fks[bh * 128 + tid] = sm[tid] + sm[tid + 128];
}

__global__ __launch_bounds__(256) void pdenom()
{
    const int bh = blockIdx.x, tid = threadIdx.x;
    __shared__ float fks[128];
    if (tid < 128) fks[tid] = g_fks[bh * 128 + tid];
    __syncthreads();
    for (int rr = 0; rr < 4; rr++) {
        int s = rr * 256 + tid;
        const bf* fh = g_fqhi + ((size_t)bh * Ss + s) * 128;
        const bf* fl = g_fqlo + ((size_t)bh * Ss + s) * 128;
        float d = 0.f;
        #pragma unroll 8
        for (int e = 0; e < 128; e++)
            d += (__bfloat162float(fh[e]) + __bfloat162float(fl[e])) * fks[e];
        g_pinv[bh * Ss + s] = 1.f / d;
    }
}

// ============================================================
// true attention: exp(q/8 . k) -> trow, 1/rowsum -> g_inv. grid(8m,32bh).
// ============================================================
__global__ __launch_bounds__(256) void true_mma(float* __restrict__ outT)
{
    __shared__ bf Ah[128*LD], Al[128*LD], Bh2[128*LD], Bl2[128*LD];
    __shared__ float rs[128];
    const int tid = threadIdx.x, lane = tid & 31, wid = tid >> 5;
    const int wm = wid & 3, wn = wid >> 2;
    const int g = lane >> 2, ti = lane & 3;
    const int bh = blockIdx.y, m0 = blockIdx.x * 128;
    float* trow = outT + (size_t)bh * Ss * Ss;
    const bf* qh = g_qhi + ((size_t)bh * Ss + m0) * 64;
    const bf* ql = g_qlo + ((size_t)bh * Ss + m0) * 64;

    if (tid < 128) rs[tid] = 0.f;
    float rsum[4] = {0.f, 0.f, 0.f, 0.f};

    for (int nt = 0; nt < 8; nt++) {
        const int n0 = nt * 128;
        const bf* kh = g_khi + ((size_t)bh * Ss + n0) * 64;
        const bf* kl = g_klo + ((size_t)bh * Ss + n0) * 64;
        float acc[2][8][4];
        #pragma unroll
        for (int i = 0; i < 2; i++)
            #pragma unroll
            for (int j = 0; j < 8; j++)
                #pragma unroll
                for (int r = 0; r < 4; r++) acc[i][j][r] = 0.f;

        #pragma unroll
        for (int k0 = 0; k0 < 64; k0 += 32) {
            ldtile32(qh + k0, 64, Ah, 128);
            ldtile32(ql + k0, 64, Al, 128);
            ldtile32(kh + k0, 64, Bh2, 128);
            ldtile32(kl + k0, 64, Bl2, 128);
            __syncthreads();
            mma_chunk<8>(acc, Ah, Al, Bh2, Bl2, wm, wn, lane);
            __syncthreads();
        }

        #pragma unroll
        for (int i = 0; i < 2; i++)
            #pragma unroll
            for (int j = 0; j < 8; j++) {
                const int col = n0 + wn * 64 + j * 8 + ti * 2;
                float e0 = __expf(acc[i][j][0]), e1 = __expf(acc[i][j][1]);
                float e2 = __expf(acc[i][j][2]), e3 = __expf(acc[i][j][3]);
                rsum[i * 2]     += e0 + e1;
                rsum[i * 2 + 1] += e2 + e3;
                const int row = m0 + wm * 32 + i * 16 + g;
                *(float2*)&trow[(size_t)row * 1024 + col]       = make_float2(e0, e1);
                *(float2*)&trow[(size_t)(row + 8) * 1024 + col] = make_float2(e2, e3);
            }
    }

    #pragma unroll
    for (int r = 0; r < 4; r++) {
        float v = rsum[r];
        v += __shfl_xor_sync(0xffffffffu, v, 1);
        v += __shfl_xor_sync(0xffffffffu, v, 2);
        if (ti == 0) atomicAdd(&rs[wm * 32 + (r >> 1) * 16 + (r & 1) * 8 + g], v);
    }
    __syncthreads();
    if (tid < 128) g_inv[bh * Ss + m0 + tid] = 1.f / rs[tid];
}

// ============================================================
// pred: (fq . fk) * pinv. grid(8m,32bh). K=128.
// ============================================================
__global__ __launch_bounds__(256) void pred_mma(float* __restrict__ outP)
{
    __shared__ bf Ah[128*LD], Al[128*LD], Bh2[128*LD], Bl2[128*LD];
    const int tid = threadIdx.x, lane = tid & 31, wid = tid >> 5;
    const int wm = wid & 3, wn = wid >> 2;
    const int g = lane >> 2, ti = lane & 3;
    const int bh = blockIdx.y, m0 = blockIdx.x * 128;
    float* prow = outP + (size_t)bh * Ss * Ss;
    const bf* fqh = g_fqhi + ((size_t)bh * Ss + m0) * 128;
    const bf* fql = g_fqlo + ((size_t)bh * Ss + m0) * 128;

    float pv[4];
    #pragma unroll
    for (int r = 0; r < 4; r++)
        pv[r] = g_pinv[bh * Ss + m0 + wm * 32 + (r >> 1) * 16 + (r & 1) * 8 + g];

    for (int nt = 0; nt < 8; nt++) {
        const int n0 = nt * 128;
        const bf* fkh = g_fkhi + ((size_t)bh * Ss + n0) * 128;
        const bf* fkl = g_fklo + ((size_t)bh * Ss + n0) * 128;
        float acc[2][8][4];
        #pragma unroll
        for (int i = 0; i < 2; i++)
            #pragma unroll
            for (int j = 0; j < 8; j++)
                #pragma unroll
                for (int r = 0; r < 4; r++) acc[i][j][r] = 0.f;

        #pragma unroll
        for (int k0 = 0; k0 < 128; k0 += 32) {
            ldtile32(fqh + k0, 128, Ah, 128);
            ldtile32(fql + k0, 128, Al, 128);
            ldtile32(fkh + k0, 128, Bh2, 128);
            ldtile32(fkl + k0, 128, Bl2, 128);
            __syncthreads();
            mma_chunk<8>(acc, Ah, Al, Bh2, Bl2, wm, wn, lane);
            __syncthreads();
        }

        #pragma unroll
        for (int i = 0; i < 2; i++)
            #pragma unroll
            for (int j = 0; j < 8; j++) {
                const int col = n0 + wn * 64 + j * 8 + ti * 2;
                const int row = m0 + wm * 32 + i * 16 + g;
                *(float2*)&prow[(size_t)row * 1024 + col] =
                    make_float2(acc[i][j][0] * pv[i * 2], acc[i][j][1] * pv[i * 2]);
                *(float2*)&prow[(size_t)(row + 8) * 1024 + col] =
                    make_float2(acc[i][j][2] * pv[i * 2 + 1], acc[i][j][3] * pv[i * 2 + 1]);
            }
    }
}

// ============================================================
// ctx = Pnorm @ V (normalize trow in place during A-load). grid(8m,32bh).
// ============================================================
__global__ __launch_bounds__(256) void ctx_mma(float* __restrict__ outT)
{
    __shared__ bf Ah[128*LD], Al[128*LD], Bh2[64*LD], Bl2[64*LD];
    __shared__ float invsm[128];
    const int tid = threadIdx.x, lane = tid & 31, wid = tid >> 5;
    const int wm = wid & 3, wn = wid >> 2;
    const int g = lane >> 2, ti = lane & 3;
    const int bh = blockIdx.y, m0 = blockIdx.x * 128;
    float* trow = outT + (size_t)bh * Ss * Ss;

    if (tid < 128) invsm[tid] = g_inv[bh * Ss + m0 + tid];
    __syncthreads();

    float acc[2][4][4];
    #pragma unroll
    for (int i = 0; i < 2; i++)
        #pragma unroll
        for (int j = 0; j < 4; j++)
            #pragma unroll
            for (int r = 0; r < 4; r++) acc[i][j][r] = 0.f;

    for (int k0 = 0; k0 < 1024; k0 += 32) {
        for (int i = tid; i < 1024; i += 256) {
            int r = i >> 3, c = (i & 7) * 4;
            size_t ga = (size_t)(m0 + r) * 1024 + k0 + c;
            float4 v = *(const float4*)&trow[ga];
            float iv = invsm[r];
            v.x *= iv; v.y *= iv; v.z *= iv; v.w *= iv;
            *(float4*)&trow[ga] = v;
            u32 h0, l0, h1, l1;
            split2(v.x, v.y, h0, l0);
            split2(v.z, v.w, h1, l1);
            *(u32*)&Ah[r * LD + c] = h0; *(u32*)&Ah[r * LD + c + 2] = h1;
            *(u32*)&Al[r * LD + c] = l0; *(u32*)&Al[r * LD + c + 2] = l1;
        }
        ldtile32(g_vthi + (size_t)bh * 64 * Ss + k0, Ss, Bh2, 64);
        ldtile32(g_vtlo + (size_t)bh * 64 * Ss + k0, Ss, Bl2, 64);
        __syncthreads();
        mma_chunk<4>(acc, Ah, Al, Bh2, Bl2, wm, wn, lane);
        __syncthreads();
    }

    #pragma unroll
    for (int i = 0; i < 2; i++)
        #pragma unroll
        for (int j = 0; j < 4; j++) {
            const int col = wn * 32 + j * 8 + ti * 2;
            #pragma unroll
            for (int hr = 0; hr < 2; hr++) {
                const int row = m0 + wm * 32 + i * 16 + g + hr * 8;
                const size_t ob = ((size_t)bh * Ss + row) * 64 + col;
                u32 h2, l2;
                split2(acc[i][j][hr * 2], acc[i][j][hr * 2 + 1], h2, l2);
                *(u32*)&g_chi[ob] = h2; *(u32*)&g_clo[ob] = l2;
            }
        }
}

// ============================================================
// outproj: out = ctx @ Wo^T + bo. grid(8n,16m).
// ============================================================
__global__ __launch_bounds__(256) void outproj_mma(const float* __restrict__ bo, float* __restrict__ out)
{
    __shared__ bf Ah[128*LD], Al[128*LD], Bh2[128*LD], Bl2[128*LD];
    const int tid = threadIdx.x, lane = tid & 31, wid = tid >> 5;
    const int wm = wid & 3, wn = wid >> 2;
    const int g = lane >> 2, ti = lane & 3;
    const int m0 = blockIdx.y * 128, n0 = blockIdx.x * 128;
    const int b_ = m0 >> 10, s0 = m0 & 1023;

    float acc[2][8][4];
    #pragma unroll
    for (int i = 0; i < 2; i++)
        #pragma unroll
        for (int j = 0; j < 8; j++)
            #pragma unroll
            for (int r = 0; r < 4; r++) acc[i][j][r] = 0.f;

    for (int k0 = 0; k0 < 1024; k0 += 32) {
        const int h = k0 >> 6, doff = k0 & 63;
        const size_t abase = ((size_t)(b_ * Hh + h) * Ss + s0) * 64 + doff;
        ldtile32(g_chi + abase, 64, Ah, 128);
        ldtile32(g_clo + abase, 64, Al, 128);
        ldtile32(g_Whi[3] + (size_t)n0 * 1024 + k0, 1024, Bh2, 128);
        ldtile32(g_Wlo[3] + (size_t)n0 * 1024 + k0, 1024, Bl2, 128);
        __syncthreads();
        mma_chunk<8>(acc, Ah, Al, Bh2, Bl2, wm, wn, lane);
        __syncthreads();
    }

    #pragma unroll
    for (int i = 0; i < 2; i++)
        #pragma unroll
        for (int j = 0; j < 8; j++) {
            const int col = n0 + wn * 64 + j * 8 + ti * 2;
            const float b0v = bo[col], b1v = bo[col + 1];
            #pragma unroll
            for (int hr = 0; hr < 2; hr++) {
                const int row = m0 + wm * 32 + i * 16 + g + hr * 8;
                *(float2*)&out[(size_t)row * 1024 + col] =
                    make_float2(acc[i][j][hr * 2] + b0v, acc[i][j][hr * 2 + 1] + b1v);
            }
        }
}

// ============================================================
extern "C" void kernel_launch(void* const* d_in, const int* in_sizes, int n_in,
                              void* d_out, int out_size)
{
    const float* hs  = (const float*)d_in[0];
    const float* Wq  = (const float*)d_in[1];
    const float* bq  = (const float*)d_in[2];
    const float* Wk  = (const float*)d_in[3];
    const float* bk  = (const float*)d_in[4];
    const float* Wv  = (const float*)d_in[5];
    const float* bv  = (const float*)d_in[6];
    const float* Wo  = (const float*)d_in[7];
    const float* bo  = (const float*)d_in[8];
    const float* Wfq = (const float*)d_in[9];
    const float* bfq = (const float*)d_in[10];
    const float* Wfk = (const float*)d_in[11];
    const float* bfk = (const float*)d_in[12];
    float* out = (float*)d_out;

    bf *Whi0, *Wlo0, *Xhi, *Xlo;
    cudaGetSymbolAddress((void**)&Whi0, g_Whi);
    cudaGetSymbolAddress((void**)&Wlo0, g_Wlo);
    cudaGetSymbolAddress((void**)&Xhi, g_Xhi);
    cudaGetSymbolAddress((void**)&Xlo, g_Xlo);

    ksplit<<<2048, 256>>>(hs, Xhi, Xlo, 524288);
    ksplit<<<1024, 256>>>(Wq, Whi0,           Wlo0,           262144);
    ksplit<<<1024, 256>>>(Wk, Whi0 + 1048576, Wlo0 + 1048576, 262144);
    ksplit<<<1024, 256>>>(Wv, Whi0 + 2097152, Wlo0 + 2097152, 262144);
    ksplit<<<1024, 256>>>(Wo, Whi0 + 3145728, Wlo0 + 3145728, 262144);

    qkv_mma<<<dim3(8, 16, 3), 256>>>(bq, bk, bv);
    feat_kernel<<<dim3(256, 2), 256>>>(Wfq, bfq, Wfk, bfk);
    vtrans<<<dim3(32, 8), 256>>>();
    fksum_kernel<<<32, 256>>>();
    pdenom<<<32, 256>>>();
    true_mma<<<dim3(8, 32), 256>>>(out + OFF_TRUE);
    pred_mma<<<dim3(8, 32), 256>>>(out + OFF_PRED);
    ctx_mma<<<dim3(8, 32), 256>>>(out + OFF_TRUE);
    outproj_mma<<<dim3(8, 16), 256>>>(bo, out);
}

// round 7
// speedup vs baseline: 1.4157x; 1.3741x over previous
#include <cuda_runtime.h>
#include <cuda_bf16.h>
#include <math.h>
#include <stdint.h>

#define Ss 1024
#define Hh 16
#define BH 32
#define LD 40
typedef __nv_bfloat16 bf;
typedef unsigned int u32;

#define OFF_PRED (2048*1024)
#define OFF_TRUE (OFF_PRED + 32*1024*1024)
#define TS (128*LD)     // elems per 128-row tile chunk

// ---------------- scratch ----------------
__device__ float g_q[BH*Ss*64], g_k[BH*Ss*64], g_v[BH*Ss*64];
__device__ bf g_qhi[BH*Ss*64], g_qlo[BH*Ss*64];     // prescaled by 1/8
__device__ bf g_khi[BH*Ss*64], g_klo[BH*Ss*64];
__device__ bf g_vthi[BH*64*Ss], g_vtlo[BH*64*Ss];   // [bh][d][s]
__device__ bf g_Xhi[2048*1024], g_Xlo[2048*1024];
__device__ bf g_Whi[4][1024*1024], g_Wlo[4][1024*1024];
__device__ bf g_fqhi[BH*Ss*128], g_fqlo[BH*Ss*128];
__device__ bf g_fkhi[BH*Ss*128], g_fklo[BH*Ss*128];
__device__ bf g_chi[BH*Ss*64], g_clo[BH*Ss*64];
__device__ float g_fks[BH*128], g_inv[BH*Ss], g_pinv[BH*Ss];

// ---------------- helpers ----------------
__device__ __forceinline__ u32 s2u(const void* p) {
    u32 r; asm("{ .reg .u64 t; cvta.to.shared.u64 t, %1; cvt.u32.u64 %0, t; }" : "=r"(r) : "l"(p)); return r;
}
__device__ __forceinline__ void cpa16(u32 dst, const void* src) {
    asm volatile("cp.async.cg.shared.global [%0], [%1], 16;" :: "r"(dst), "l"(src));
}
__device__ __forceinline__ void cpcommit() { asm volatile("cp.async.commit_group;" ::: "memory"); }
__device__ __forceinline__ void cpwait0() { asm volatile("cp.async.wait_group 0;" ::: "memory"); }
__device__ __forceinline__ void cpwait1() { asm volatile("cp.async.wait_group 1;" ::: "memory"); }
__device__ __forceinline__ void ldsm4(u32 a, u32& r0, u32& r1, u32& r2, u32& r3) {
    asm volatile("ldmatrix.sync.aligned.m8n8.x4.shared.b16 {%0,%1,%2,%3}, [%4];"
        : "=r"(r0), "=r"(r1), "=r"(r2), "=r"(r3) : "r"(a));
}
__device__ __forceinline__ void mmabf(float* d, const u32* a, const u32* b) {
    asm volatile("mma.sync.aligned.m16n8k16.row.col.f32.bf16.bf16.f32 "
        "{%0,%1,%2,%3}, {%4,%5,%6,%7}, {%8,%9}, {%0,%1,%2,%3};"
        : "+f"(d[0]), "+f"(d[1]), "+f"(d[2]), "+f"(d[3])
        : "r"(a[0]), "r"(a[1]), "r"(a[2]), "r"(a[3]), "r"(b[0]), "r"(b[1]));
}
__device__ __forceinline__ void split2(float x, float y, u32& hi, u32& lo) {
    bf hx = __float2bfloat16(x), hy = __float2bfloat16(y);
    bf lx = __float2bfloat16(x - __bfloat162float(hx));
    bf ly = __float2bfloat16(y - __bfloat162float(hy));
    hi = (u32)__bfloat16_as_ushort(hx) | ((u32)__bfloat16_as_ushort(hy) << 16);
    lo = (u32)__bfloat16_as_ushort(lx) | ((u32)__bfloat16_as_ushort(ly) << 16);
}

// async: gmem (row stride ldg elems) -> smem [rows][LD], one 32-k chunk
__device__ __forceinline__ void ldtile32a(const bf* __restrict__ g, int ldg, u32 s, int rows) {
    for (int i = threadIdx.x; i < rows * 4; i += 256) {
        int r = i >> 2, c = (i & 3) << 3;
        cpa16(s + (u32)((r * LD + c) << 1), g + (size_t)r * ldg + c);
    }
}

// warp computes 32(m) x NF*8(n) over a 32-k chunk, hi/lo 3-product emulation
template<int NF>
__device__ __forceinline__ void mma_chunk(
    float (&acc)[2][NF][4],
    const bf* Ah, const bf* Al, const bf* Bh, const bf* Bl,
    int wm, int wn, int lane)
{
    const u32 ahb = s2u(Ah) + (u32)(wm * 32 * LD * 2);
    const u32 alb = s2u(Al) + (u32)(wm * 32 * LD * 2);
    const u32 bhb = s2u(Bh) + (u32)(wn * NF * 8 * LD * 2);
    const u32 blb = s2u(Bl) + (u32)(wn * NF * 8 * LD * 2);
    const u32 aoff = (u32)(((lane & 15) * LD + ((lane >> 4) << 3)) * 2);
    const u32 boff = (u32)((((lane & 7) + ((lane >> 4) << 3)) * LD + (((lane >> 3) & 1) << 3)) * 2);
    #pragma unroll
    for (int kk = 0; kk < 32; kk += 16) {
        u32 ah[2][4], al[2][4], bhf[NF][2], blf[NF][2];
        #pragma unroll
        for (int i = 0; i < 2; i++) {
            ldsm4(ahb + aoff + kk * 2 + i * 16 * LD * 2, ah[i][0], ah[i][1], ah[i][2], ah[i][3]);
            ldsm4(alb + aoff + kk * 2 + i * 16 * LD * 2, al[i][0], al[i][1], al[i][2], al[i][3]);
        }
        #pragma unroll
        for (int j = 0; j < NF; j += 2) {
            ldsm4(bhb + boff + kk * 2 + j * 8 * LD * 2, bhf[j][0], bhf[j][1], bhf[j+1][0], bhf[j+1][1]);
            ldsm4(blb + boff + kk * 2 + j * 8 * LD * 2, blf[j][0], blf[j][1], blf[j+1][0], blf[j+1][1]);
        }
        #pragma unroll
        for (int i = 0; i < 2; i++)
            #pragma unroll
            for (int j = 0; j < NF; j++) {
                mmabf(acc[i][j], ah[i], bhf[j]);
                mmabf(acc[i][j], ah[i], blf[j]);
                mmabf(acc[i][j], al[i], bhf[j]);
            }
    }
}

extern __shared__ __align__(16) char dynsm[];

// ============================================================
__global__ __launch_bounds__(256) void ksplit(const float* __restrict__ src,
                                              bf* __restrict__ hi, bf* __restrict__ lo, int n4)
{
    int i = blockIdx.x * 256 + threadIdx.x;
    if (i < n4) {
        float4 v = ((const float4*)src)[i];
        u32 h0, l0, h1, l1;
        split2(v.x, v.y, h0, l0);
        split2(v.z, v.w, h1, l1);
        ((uint2*)hi)[i] = make_uint2(h0, h1);
        ((uint2*)lo)[i] = make_uint2(l0, l1);
    }
}

// ============================================================
// QKV: C = X @ W^T + b. grid(8n,16m,3z). 2-stage pipeline, 80KB smem.
// ============================================================
__global__ __launch_bounds__(256) void qkv_mma(
    const float* __restrict__ bq, const float* __restrict__ bk, const float* __restrict__ bv)
{
    bf* buf = (bf*)dynsm;   // stage s at s*4*TS: Ah, Al, Bh, Bl
    const int tid = threadIdx.x, lane = tid & 31, wid = tid >> 5;
    const int wm = wid & 3, wn = wid >> 2;
    const int g = lane >> 2, ti = lane & 3;
    const int z = blockIdx.z, m0 = blockIdx.y * 128, n0 = blockIdx.x * 128;
    const bf* Whi = g_Whi[z]; const bf* Wlo = g_Wlo[z];
    const float* bias = z == 0 ? bq : (z == 1 ? bk : bv);

    float acc[2][8][4];
    #pragma unroll
    for (int i = 0; i < 2; i++)
        #pragma unroll
        for (int j = 0; j < 8; j++)
            #pragma unroll
            for (int r = 0; r < 4; r++) acc[i][j][r] = 0.f;

    auto issue = [&](int c) {
        bf* p = buf + (c & 1) * 4 * TS;
        const int k0 = c * 32;
        ldtile32a(g_Xhi + (size_t)m0 * 1024 + k0, 1024, s2u(p), 128);
        ldtile32a(g_Xlo + (size_t)m0 * 1024 + k0, 1024, s2u(p + TS), 128);
        ldtile32a(Whi + (size_t)n0 * 1024 + k0, 1024, s2u(p + 2 * TS), 128);
        ldtile32a(Wlo + (size_t)n0 * 1024 + k0, 1024, s2u(p + 3 * TS), 128);
        cpcommit();
    };
    issue(0); issue(1);

    for (int c = 0; c < 32; c++) {
        if (c == 31) cpwait0(); else cpwait1();
        __syncthreads();
        bf* p = buf + (c & 1) * 4 * TS;
        mma_chunk<8>(acc, p, p + TS, p + 2 * TS, p + 3 * TS, wm, wn, lane);
        __syncthreads();
        if (c + 2 < 32) issue(c + 2);
    }

    #pragma unroll
    for (int i = 0; i < 2; i++)
        #pragma unroll
        for (int j = 0; j < 8; j++) {
            const int col = n0 + wn * 64 + j * 8 + ti * 2;
            const int h = col >> 6, d = col & 63;
            const float b0v = bias[col], b1v = bias[col + 1];
            #pragma unroll
            for (int hr = 0; hr < 2; hr++) {
                const int row = m0 + wm * 32 + i * 16 + g + hr * 8;
                const int b_ = row >> 10, s = row & 1023;
                const size_t ob = ((size_t)(b_ * Hh + h) * Ss + s) * 64 + d;
                const float v0 = acc[i][j][hr * 2] + b0v, v1 = acc[i][j][hr * 2 + 1] + b1v;
                u32 h2, l2;
                if (z == 0) {
                    *(float2*)&g_q[ob] = make_float2(v0, v1);
                    split2(v0 * 0.125f, v1 * 0.125f, h2, l2);
                    *(u32*)&g_qhi[ob] = h2; *(u32*)&g_qlo[ob] = l2;
                } else if (z == 1) {
                    *(float2*)&g_k[ob] = make_float2(v0, v1);
                    split2(v0, v1, h2, l2);
                    *(u32*)&g_khi[ob] = h2; *(u32*)&g_klo[ob] = l2;
                } else {
                    *(float2*)&g_v[ob] = make_float2(v0, v1);
                }
            }
        }
}

// ============================================================
// feature map -> split bf16
// ============================================================
__global__ __launch_bounds__(256) void feat_kernel(
    const float* __restrict__ Wfq, const float* __restrict__ bfq,
    const float* __restrict__ Wfk, const float* __restrict__ bfk)
{
    const float* Wf; const float* bfp; const float* src; bf *dh, *dl;
    if (blockIdx.y == 0) { Wf = Wfq; bfp = bfq; src = g_q; dh = g_fqhi; dl = g_fqlo; }
    else                 { Wf = Wfk; bfp = bfk; src = g_k; dh = g_fkhi; dl = g_fklo; }

    __shared__ float Wt[64][65];
    __shared__ float bsm[64];
    __shared__ float qs[4][64];

    const int tid = threadIdx.x;
    #pragma unroll
    for (int p = 0; p < 16; p++) {
        int idx = p * 256 + tid;
        Wt[idx & 63][idx >> 6] = Wf[idx];
    }
    if (tid < 64) bsm[tid] = bfp[tid];

    const int rowbase = blockIdx.x * 128;
    const int e = tid & 63, rr = tid >> 6;

    for (int r0 = 0; r0 < 128; r0 += 4) {
        __syncthreads();
        int row = rowbase + r0 + rr;
        qs[rr][e] = src[(size_t)row * 64 + e];
        __syncthreads();
        float y = bsm[e];
        #pragma unroll
        for (int d = 0; d < 64; d++) y += Wt[d][e] * qs[rr][d];
        float e0 = expf(y), e1 = expf(-y);
        bf h0 = __float2bfloat16(e0), h1 = __float2bfloat16(e1);
        size_t o = (size_t)row * 128 + e;
        dh[o] = h0;      dl[o] = __float2bfloat16(e0 - __bfloat162float(h0));
        dh[o + 64] = h1; dl[o + 64] = __float2bfloat16(e1 - __bfloat162float(h1));
    }
}

// ============================================================
// V transpose + split
// ============================================================
__global__ __launch_bounds__(256) void vtrans()
{
    __shared__ float t[128][65];
    const int bh = blockIdx.x, s0 = blockIdx.y * 128, tid = threadIdx.x;
    for (int i = tid; i < 2048; i += 256) {
        int r = i >> 4, c = (i & 15) * 4;
        float4 v = *(const float4*)&g_v[((size_t)bh * Ss + s0 + r) * 64 + c];
        t[r][c] = v.x; t[r][c+1] = v.y; t[r][c+2] = v.z; t[r][c+3] = v.w;
    }
    __syncthreads();
    for (int i = tid; i < 1024; i += 256) {
        int d = i >> 4, sb = (i & 15) * 8;
        __align__(16) unsigned short hh[8], ll[8];
        #pragma unroll
        for (int j = 0; j < 8; j++) {
            float x = t[sb + j][d];
            bf h = __float2bfloat16(x);
            hh[j] = __bfloat16_as_ushort(h);
            ll[j] = __bfloat16_as_ushort(__float2bfloat16(x - __bfloat162float(h)));
        }
        size_t ob = ((size_t)bh * 64 + d) * Ss + s0 + sb;
        *(uint4*)&g_vthi[ob] = *(uint4*)hh;
        *(uint4*)&g_vtlo[ob] = *(uint4*)ll;
    }
}

// ============================================================
__global__ __launch_bounds__(256) void fksum_kernel()
{
    const int bh = blockIdx.x, tid = threadIdx.x;
    const int e = tid & 127, part = tid >> 7;
    const bf* fh = g_fkhi + (size_t)bh * Ss * 128;
    const bf* fl = g_fklo + (size_t)bh * Ss * 128;
    float s = 0.f;
    for (int r = part; r < 1024; r += 2) {
        size_t o = (size_t)r * 128 + e;
        s += __bfloat162float(fh[o]) + __bfloat162float(fl[o]);
    }
    __shared__ float sm[256];
    sm[tid] = s;
    __syncthreads();
    if (tid < 128) g_fks[bh * 128 + tid] = sm[tid] + sm[tid + 128];
}

__global__ __launch_bounds__(256) void pdenom()
{
    const int bh = blockIdx.x, tid = threadIdx.x;
    __shared__ float fks[128];
    if (tid < 128) fks[tid] = g_fks[bh * 128 + tid];
    __syncthreads();
    for (int rr = 0; rr < 4; rr++) {
        int s = rr * 256 + tid;
        const bf* fh = g_fqhi + ((size_t)bh * Ss + s) * 128;
        const bf* fl = g_fqlo + ((size_t)bh * Ss + s) * 128;
        float d = 0.f;
        #pragma unroll 8
        for (int e = 0; e < 128; e++)
            d += (__bfloat162float(fh[e]) + __bfloat162float(fl[e])) * fks[e];
        g_pinv[bh * Ss + s] = 1.f / d;
    }
}

// ============================================================
// true attention. Q resident (40KB), K streamed 2-stage. grid(8m,32bh).
// ============================================================
__global__ __launch_bounds__(256) void true_mma(float* __restrict__ outT)
{
    bf* qb = (bf*)dynsm;            // Qh0,Ql0,Qh1,Ql1
    bf* kb = (bf*)dynsm;            // set below (elem arithmetic)
    __shared__ float rs[128];
    const int tid = threadIdx.x, lane = tid & 31, wid = tid >> 5;
    const int wm = wid & 3, wn = wid >> 2;
    const int g = lane >> 2, ti = lane & 3;
    const int bh = blockIdx.y, m0 = blockIdx.x * 128;
    float* trow = outT + (size_t)bh * Ss * Ss;
    const bf* qh = g_qhi + ((size_t)bh * Ss + m0) * 64;
    const bf* ql = g_qlo + ((size_t)bh * Ss + m0) * 64;

    kb = (bf*)dynsm + 4 * TS;       // stage area after q (elem offsets)

    if (tid < 128) rs[tid] = 0.f;

    // group 0: resident q (2 chunks x hi/lo)
    ldtile32a(qh,      64, s2u(qb),          128);
    ldtile32a(ql,      64, s2u(qb + TS),     128);
    ldtile32a(qh + 32, 64, s2u(qb + 2 * TS), 128);
    ldtile32a(ql + 32, 64, s2u(qb + 3 * TS), 128);
    cpcommit();

    auto issueK = [&](int nt) {
        bf* p = kb + (nt & 1) * 4 * TS;
        const bf* kh = g_khi + ((size_t)bh * Ss + nt * 128) * 64;
        const bf* kl = g_klo + ((size_t)bh * Ss + nt * 128) * 64;
        ldtile32a(kh,      64, s2u(p),          128);
        ldtile32a(kl,      64, s2u(p + TS),     128);
        ldtile32a(kh + 32, 64, s2u(p + 2 * TS), 128);
        ldtile32a(kl + 32, 64, s2u(p + 3 * TS), 128);
        cpcommit();
    };
    issueK(0); issueK(1);

    float rsum[4];
    for (int nt = 0; nt < 8; nt++) {
        if (nt == 7) cpwait0(); else cpwait1();
        __syncthreads();
        float acc[2][8][4];
        #pragma unroll
        for (int i = 0; i < 2; i++)
            #pragma unroll
            for (int j = 0; j < 8; j++)
                #pragma unroll
                for (int r = 0; r < 4; r++) acc[i][j][r] = 0.f;

        bf* p = kb + (nt & 1) * 4 * TS;
        mma_chunk<8>(acc, qb,          qb + TS,     p,          p + TS,     wm, wn, lane);
        mma_chunk<8>(acc, qb + 2 * TS, qb + 3 * TS, p + 2 * TS, p + 3 * TS, wm, wn, lane);
        __syncthreads();
        if (nt + 2 < 8) issueK(nt + 2);

        const int n0 = nt * 128;
        #pragma unroll
        for (int r = 0; r < 4; r++) rsum[r] = 0.f;
        #pragma unroll
        for (int i = 0; i < 2; i++)
            #pragma unroll
            for (int j = 0; j < 8; j++) {
                const int col = n0 + wn * 64 + j * 8 + ti * 2;
                float e0 = __expf(acc[i][j][0]), e1 = __expf(acc[i][j][1]);
                float e2 = __expf(acc[i][j][2]), e3 = __expf(acc[i][j][3]);
                rsum[i * 2]     += e0 + e1;
                rsum[i * 2 + 1] += e2 + e3;
                const int row = m0 + wm * 32 + i * 16 + g;
                *(float2*)&trow[(size_t)row * 1024 + col]       = make_float2(e0, e1);
                *(float2*)&trow[(size_t)(row + 8) * 1024 + col] = make_float2(e2, e3);
            }
        #pragma unroll
        for (int r = 0; r < 4; r++) {
            float v = rsum[r];
            v += __shfl_xor_sync(0xffffffffu, v, 1);
            v += __shfl_xor_sync(0xffffffffu, v, 2);
            if (ti == 0) atomicAdd(&rs[wm * 32 + (r >> 1) * 16 + (r & 1) * 8 + g], v);
        }
    }
    __syncthreads();
    if (tid < 128) g_inv[bh * Ss + m0 + tid] = 1.f / rs[tid];
}

// ============================================================
// pred: fq resident (80KB), fk streamed half-tiles. grid(8m,32bh).
// ============================================================
__global__ __launch_bounds__(256) void pred_mma(float* __restrict__ outP)
{
    bf* fq = (bf*)dynsm;                 // Fqh[4 chunks] then Fql[4 chunks]
    bf* kb = (bf*)dynsm + 8 * TS;        // stage s: Kh0,Kl0,Kh1,Kl1
    const int tid = threadIdx.x, lane = tid & 31, wid = tid >> 5;
    const int wm = wid & 3, wn = wid >> 2;
    const int g = lane >> 2, ti = lane & 3;
    const int bh = blockIdx.y, m0 = blockIdx.x * 128;
    float* prow = outP + (size_t)bh * Ss * Ss;
    const bf* fqh = g_fqhi + ((size_t)bh * Ss + m0) * 128;
    const bf* fql = g_fqlo + ((size_t)bh * Ss + m0) * 128;

    // group 0: resident fq
    #pragma unroll
    for (int kc = 0; kc < 4; kc++) {
        ldtile32a(fqh + kc * 32, 128, s2u(fq + kc * TS),       128);
        ldtile32a(fql + kc * 32, 128, s2u(fq + (4 + kc) * TS), 128);
    }
    cpcommit();

    auto issueFK = [&](int st) {   // st = nt*2 + half
        bf* p = kb + (st & 1) * 4 * TS;
        const int nt = st >> 1, half = st & 1;
        const bf* kh = g_fkhi + ((size_t)bh * Ss + nt * 128) * 128 + half * 64;
        const bf* kl = g_fklo + ((size_t)bh * Ss + nt * 128) * 128 + half * 64;
        ldtile32a(kh,      128, s2u(p),          128);
        ldtile32a(kl,      128, s2u(p + TS),     128);
        ldtile32a(kh + 32, 128, s2u(p + 2 * TS), 128);
        ldtile32a(kl + 32, 128, s2u(p + 3 * TS), 128);
        cpcommit();
    };
    issueFK(0); issueFK(1);

    float pv[4];
    #pragma unroll
    for (int r = 0; r < 4; r++)
        pv[r] = g_pinv[bh * Ss + m0 + wm * 32 + (r >> 1) * 16 + (r & 1) * 8 + g];

    float acc[2][8][4];
    for (int st = 0; st < 16; st++) {
        const int nt = st >> 1, half = st & 1;
        if (half == 0) {
            #pragma unroll
            for (int i = 0; i < 2; i++)
                #pragma unroll
                for (int j = 0; j < 8; j++)
                    #pragma unroll
                    for (int r = 0; r < 4; r++) acc[i][j][r] = 0.f;
        }
        if (st == 15) cpwait0(); else cpwait1();
        __syncthreads();
        bf* p = kb + (st & 1) * 4 * TS;
        const int kc = half * 2;
        mma_chunk<8>(acc, fq + kc * TS,       fq + (4 + kc) * TS,     p,          p + TS,     wm, wn, lane);
        mma_chunk<8>(acc, fq + (kc + 1) * TS, fq + (4 + kc + 1) * TS, p + 2 * TS, p + 3 * TS, wm, wn, lane);
        __syncthreads();
        if (st + 2 < 16) issueFK(st + 2);

        if (half == 1) {
            const int n0 = nt * 128;
            #pragma unroll
            for (int i = 0; i < 2; i++)
                #pragma unroll
                for (int j = 0; j < 8; j++) {
                    const int col = n0 + wn * 64 + j * 8 + ti * 2;
                    const int row = m0 + wm * 32 + i * 16 + g;
                    *(float2*)&prow[(size_t)row * 1024 + col] =
                        make_float2(acc[i][j][0] * pv[i * 2], acc[i][j][1] * pv[i * 2]);
                    *(float2*)&prow[(size_t)(row + 8) * 1024 + col] =
                        make_float2(acc[i][j][2] * pv[i * 2 + 1], acc[i][j][3] * pv[i * 2 + 1]);
                }
        }
    }
}

// ============================================================
// ctx = Pnorm @ V. trow staged via cp.async, normalized out of smem.
// FIX (R7): issue(c+2) moved AFTER mma_chunk + sync — it overwrites
// stage (c&1) B tiles that the mma for chunk c reads.
// ============================================================
__global__ __launch_bounds__(256) void ctx_mma(float* __restrict__ outT)
{
    float* tr = (float*)dynsm;                        // 2 stages x 4096 floats
    bf* ab = (bf*)(dynsm + 32768);                    // Ah, Al (single pair)
    bf* bb = (bf*)(dynsm + 32768 + 2 * TS * 2);       // stage s: Bh, Bl (64 rows)
    const int HT = 64 * LD;
    __shared__ float invsm[128];
    const int tid = threadIdx.x, lane = tid & 31, wid = tid >> 5;
    const int wm = wid & 3, wn = wid >> 2;
    const int g = lane >> 2, ti = lane & 3;
    const int bh = blockIdx.y, m0 = blockIdx.x * 128;
    float* trow = outT + (size_t)bh * Ss * Ss;

    if (tid < 128) invsm[tid] = g_inv[bh * Ss + m0 + tid];

    auto issue = [&](int c) {
        const int st = c & 1;
        u32 ts = s2u(tr + st * 4096);
        for (int i = tid; i < 1024; i += 256) {
            int r = i >> 3, c4 = (i & 7) * 4;
            cpa16(ts + (u32)((r * 32 + c4) * 4), &trow[(size_t)(m0 + r) * 1024 + c * 32 + c4]);
        }
        bf* p = bb + st * 2 * HT;
        ldtile32a(g_vthi + (size_t)bh * 64 * Ss + c * 32, Ss, s2u(p), 64);
        ldtile32a(g_vtlo + (size_t)bh * 64 * Ss + c * 32, Ss, s2u(p + HT), 64);
        cpcommit();
    };
    issue(0); issue(1);

    float acc[2][4][4];
    #pragma unroll
    for (int i = 0; i < 2; i++)
        #pragma unroll
        for (int j = 0; j < 4; j++)
            #pragma unroll
            for (int r = 0; r < 4; r++) acc[i][j][r] = 0.f;

    for (int c = 0; c < 32; c++) {
        if (c == 31) cpwait0(); else cpwait1();
        __syncthreads();
        const int st = c & 1;
        float* trs = tr + st * 4096;
        // transform: normalize + writeback + split into Ah/Al
        for (int i = tid; i < 1024; i += 256) {
            int r = i >> 3, c4 = (i & 7) * 4;
            float4 v = *(float4*)&trs[r * 32 + c4];
            float iv = invsm[r];
            v.x *= iv; v.y *= iv; v.z *= iv; v.w *= iv;
            *(float4*)&trow[(size_t)(m0 + r) * 1024 + c * 32 + c4] = v;
            u32 h0, l0, h1, l1;
            split2(v.x, v.y, h0, l0);
            split2(v.z, v.w, h1, l1);
            *(u32*)&ab[r * LD + c4] = h0;      *(u32*)&ab[r * LD + c4 + 2] = h1;
            *(u32*)&ab[TS + r * LD + c4] = l0; *(u32*)&ab[TS + r * LD + c4 + 2] = l1;
        }
        __syncthreads();
        bf* p = bb + st * 2 * HT;
        mma_chunk<4>(acc, ab, ab + TS, p, p + HT, wm, wn, lane);
        __syncthreads();
        if (c + 2 < 32) issue(c + 2);
    }

    #pragma unroll
    for (int i = 0; i < 2; i++)
        #pragma unroll
        for (int j = 0; j < 4; j++) {
            const int col = wn * 32 + j * 8 + ti * 2;
            #pragma unroll
            for (int hr = 0; hr < 2; hr++) {
                const int row = m0 + wm * 32 + i * 16 + g + hr * 8;
                const size_t ob = ((size_t)bh * Ss + row) * 64 + col;
                u32 h2, l2;
                split2(acc[i][j][hr * 2], acc[i][j][hr * 2 + 1], h2, l2);
                *(u32*)&g_chi[ob] = h2; *(u32*)&g_clo[ob] = l2;
            }
        }
}

// ============================================================
// outproj: out = ctx @ Wo^T + bo. grid(8n,16m). pipelined.
// ============================================================
__global__ __launch_bounds__(256) void outproj_mma(const float* __restrict__ bo, float* __restrict__ out)
{
    bf* buf = (bf*)dynsm;
    const int tid = threadIdx.x, lane = tid & 31, wid = tid >> 5;
    const int wm = wid & 3, wn = wid >> 2;
    const int g = lane >> 2, ti = lane & 3;
    const int m0 = blockIdx.y * 128, n0 = blockIdx.x * 128;
    const int b_ = m0 >> 10, s0 = m0 & 1023;

    float acc[2][8][4];
    #pragma unroll
    for (int i = 0; i < 2; i++)
        #pragma unroll
        for (int j = 0; j < 8; j++)
            #pragma unroll
            for (int r = 0; r < 4; r++) acc[i][j][r] = 0.f;

    auto issue = [&](int c) {
        bf* p = buf + (c & 1) * 4 * TS;
        const int k0 = c * 32;
        const int h = k0 >> 6, doff = k0 & 63;
        const size_t abase = ((size_t)(b_ * Hh + h) * Ss + s0) * 64 + doff;
        ldtile32a(g_chi + abase, 64, s2u(p), 128);
        ldtile32a(g_clo + abase, 64, s2u(p + TS), 128);
        ldtile32a(g_Whi[3] + (size_t)n0 * 1024 + k0, 1024, s2u(p + 2 * TS), 128);
        ldtile32a(g_Wlo[3] + (size_t)n0 * 1024 + k0, 1024, s2u(p + 3 * TS), 128);
        cpcommit();
    };
    issue(0); issue(1);

    for (int c = 0; c < 32; c++) {
        if (c == 31) cpwait0(); else cpwait1();
        __syncthreads();
        bf* p = buf + (c & 1) * 4 * TS;
        mma_chunk<8>(acc, p, p + TS, p + 2 * TS, p + 3 * TS, wm, wn, lane);
        __syncthreads();
        if (c + 2 < 32) issue(c + 2);
    }

    #pragma unroll
    for (int i = 0; i < 2; i++)
        #pragma unroll
        for (int j = 0; j < 8; j++) {
            const int col = n0 + wn * 64 + j * 8 + ti * 2;
            const float b0v = bo[col], b1v = bo[col + 1];
            #pragma unroll
            for (int hr = 0; hr < 2; hr++) {
                const int row = m0 + wm * 32 + i * 16 + g + hr * 8;
                *(float2*)&out[(size_t)row * 1024 + col] =
                    make_float2(acc[i][j][hr * 2] + b0v, acc[i][j][hr * 2 + 1] + b1v);
            }
        }
}

// ============================================================
extern "C" void kernel_launch(void* const* d_in, const int* in_sizes, int n_in,
                              void* d_out, int out_size)
{
    const float* hs  = (const float*)d_in[0];
    const float* Wq  = (const float*)d_in[1];
    const float* bq  = (const float*)d_in[2];
    const float* Wk  = (const float*)d_in[3];
    const float* bk  = (const float*)d_in[4];
    const float* Wv  = (const float*)d_in[5];
    const float* bv  = (const float*)d_in[6];
    const float* Wo  = (const float*)d_in[7];
    const float* bo  = (const float*)d_in[8];
    const float* Wfq = (const float*)d_in[9];
    const float* bfq = (const float*)d_in[10];
    const float* Wfk = (const float*)d_in[11];
    const float* bfk = (const float*)d_in[12];
    float* out = (float*)d_out;

    const int SM_GEMM = 8 * TS * 2;          // 81920
    const int SM_TRUE = 12 * TS * 2;         // 122880
    const int SM_PRED = 16 * TS * 2;         // 163840
    const int SM_CTX  = 32768 + 4 * TS * 2 + 4 * 64 * LD * 2;  // 94208
    cudaFuncSetAttribute(qkv_mma,     cudaFuncAttributeMaxDynamicSharedMemorySize, SM_GEMM);
    cudaFuncSetAttribute(true_mma,    cudaFuncAttributeMaxDynamicSharedMemorySize, SM_TRUE);
    cudaFuncSetAttribute(pred_mma,    cudaFuncAttributeMaxDynamicSharedMemorySize, SM_PRED);
    cudaFuncSetAttribute(ctx_mma,     cudaFuncAttributeMaxDynamicSharedMemorySize, SM_CTX);
    cudaFuncSetAttribute(outproj_mma, cudaFuncAttributeMaxDynamicSharedMemorySize, SM_GEMM);

    bf *Whi0, *Wlo0, *Xhi, *Xlo;
    cudaGetSymbolAddress((void**)&Whi0, g_Whi);
    cudaGetSymbolAddress((void**)&Wlo0, g_Wlo);
    cudaGetSymbolAddress((void**)&Xhi, g_Xhi);
    cudaGetSymbolAddress((void**)&Xlo, g_Xlo);

    ksplit<<<2048, 256>>>(hs, Xhi, Xlo, 524288);
    ksplit<<<1024, 256>>>(Wq, Whi0,           Wlo0,           262144);
    ksplit<<<1024, 256>>>(Wk, Whi0 + 1048576, Wlo0 + 1048576, 262144);
    ksplit<<<1024, 256>>>(Wv, Whi0 + 2097152, Wlo0 + 2097152, 262144);
    ksplit<<<1024, 256>>>(Wo, Whi0 + 3145728, Wlo0 + 3145728, 262144);

    qkv_mma<<<dim3(8, 16, 3), 256, SM_GEMM>>>(bq, bk, bv);
    feat_kernel<<<dim3(256, 2), 256>>>(Wfq, bfq, Wfk, bfk);
    vtrans<<<dim3(32, 8), 256>>>();
    fksum_kernel<<<32, 256>>>();
    pdenom<<<32, 256>>>();
    true_mma<<<dim3(8, 32), 256, SM_TRUE>>>(out + OFF_TRUE);
    pred_mma<<<dim3(8, 32), 256, SM_PRED>>>(out + OFF_PRED);
    ctx_mma<<<dim3(8, 32), 256, SM_CTX>>>(out + OFF_TRUE);
    outproj_mma<<<dim3(8, 16), 256, SM_GEMM>>>(bo, out);
}